// round 17
// baseline (speedup 1.0000x reference)
#include <cuda_runtime.h>

typedef unsigned long long ull;

#define T_LEN 512
#define NB    32            // batch rows per CTA
#define NTH   256           // 32 col-chunks (8 cols) x 8 row-groups (4 rows)
#define GC    256           // padded gate cols: col = 4*u + g, u < 64 (real u < 50)

// ---- shared memory layout (float offsets) ----
#define OFF_WT1  0                       // [100][256]: k<50 Wih1^T, k>=50 Whh1^T (prescaled)
#define OFF_WT0  (OFF_WT1 + 100*GC)     // [50][256]: Whh0^T (prescaled)
#define OFF_WX0  (OFF_WT0 + 50*GC)      // [256] Wih0 column (prescaled)
#define OFF_B0   (OFF_WX0 + GC)
#define OFF_B1   (OFF_B0  + GC)
#define OFF_HS   (OFF_B1  + GC)         // 4 buffers x [50 units][32 rows] ull splat (h,h)
                                         //   order: h0[0], h0[1], h1[0], h1[1]; 3200 floats each
#define OFF_FC   (OFF_HS + 4*3200)
#define SMEMF    (OFF_FC + 64)          // 52032 floats = 208128 B

#define SCALE_S (-1.4426950408889634f)  // sigmoid gates: sig(x)=rcp(1+ex2(x*-log2e))
#define SCALE_T (-2.8853900817779268f)  // tanh: tanh(x)=2*rcp(1+ex2(x*-2log2e))-1

// ---- packed f32x2 + MUFU helpers ----
__device__ __forceinline__ ull pack2(float x, float y) {
    ull r; asm("mov.b64 %0, {%1, %2};" : "=l"(r) : "f"(x), "f"(y)); return r;
}
__device__ __forceinline__ void unpack2(ull v, float& x, float& y) {
    asm("mov.b64 {%0, %1}, %2;" : "=f"(x), "=f"(y) : "l"(v));
}
__device__ __forceinline__ void fma2(ull& d, ull a, ull b) {
    asm("fma.rn.f32x2 %0, %1, %2, %0;" : "+l"(d) : "l"(a), "l"(b));
}
__device__ __forceinline__ float fex2(float x) {
    float r; asm("ex2.approx.f32 %0, %1;" : "=f"(r) : "f"(x)); return r;
}
__device__ __forceinline__ float frcp(float x) {
    float r; asm("rcp.approx.f32 %0, %1;" : "=f"(r) : "f"(x)); return r;
}

// acc layout: a[r*4 + p], r = row 0..3, p = col-pair 0..3 (8 cols)
// 8 cols x 4 rows += hh[r] * w[8]; weights = 2 x LDS.128; hh pre-splatted (h,h)
__device__ __forceinline__ void mvk(ull* a, const ull* hh, const float* w) {
    const ulonglong2* w2 = reinterpret_cast<const ulonglong2*>(w);
    ulonglong2 va = w2[0], vb = w2[1];
    #pragma unroll
    for (int r = 0; r < 4; ++r) {
        fma2(a[r*4 + 0], hh[r], va.x);
        fma2(a[r*4 + 1], hh[r], va.y);
        fma2(a[r*4 + 2], hh[r], vb.x);
        fma2(a[r*4 + 3], hh[r], vb.y);
    }
}
__device__ __forceinline__ void initb16(ull* a, const float* b) {
    const ulonglong2* b2 = reinterpret_cast<const ulonglong2*>(b);
    ulonglong2 v0 = b2[0], v1 = b2[1];
    #pragma unroll
    for (int r = 0; r < 4; ++r) {
        a[r*4 + 0] = v0.x; a[r*4 + 1] = v0.y;
        a[r*4 + 2] = v1.x; a[r*4 + 3] = v1.y;
    }
}
// load 4 pre-splatted h pairs (32B) for this thread's rows: 2 x LDS.128
__device__ __forceinline__ void hload4(const ull* hs, int idx, ull* hh) {
    ulonglong2 v0 = *reinterpret_cast<const ulonglong2*>(hs + idx);
    ulonglong2 v1 = *reinterpret_cast<const ulonglong2*>(hs + idx + 2);
    hh[0] = v0.x; hh[1] = v0.y; hh[2] = v1.x; hh[3] = v1.y;
}

// unit J (0..1) LSTM cell update for 4 rows; gates prescaled
// (i/f/o by -log2e, g by -2log2e); writes 4 splat pairs as 2 x STS.128
template<int J>
__device__ __forceinline__ void act_u(const ull* a, float* cs, ull* hs, int u0, int g) {
    float hv[4];
    #pragma unroll
    for (int r = 0; r < 4; ++r) {
        float gi, gf, gg, go;
        unpack2(a[r*4 + 2*J],     gi, gf);
        unpack2(a[r*4 + 2*J + 1], gg, go);
        float si = frcp(1.f + fex2(gi));
        float sf = frcp(1.f + fex2(gf));
        float sg = frcp(1.f + fex2(gg));
        float so = frcp(1.f + fex2(go));
        float tg = fmaf(2.f, sg, -1.f);
        float cn = fmaf(sf, cs[J*4 + r], si * tg);
        cs[J*4 + r] = cn;
        float tc = fmaf(2.f, frcp(1.f + fex2(SCALE_T * cn)), -1.f);
        hv[r] = so * tc;
    }
    if (u0 + J < 50) {
        ull* dst = hs + (u0 + J)*32 + g*4;
        ulonglong2 s0, s1;
        s0.x = pack2(hv[0], hv[0]);  s0.y = pack2(hv[1], hv[1]);
        s1.x = pack2(hv[2], hv[2]);  s1.y = pack2(hv[3], hv[3]);
        *reinterpret_cast<ulonglong2*>(dst)     = s0;   // STS.128
        *reinterpret_cast<ulonglong2*>(dst + 2) = s1;   // STS.128
    }
}

__global__ void __launch_bounds__(NTH, 1)
lstm_v7_kernel(const float* __restrict__ x,
               const float* __restrict__ Wih0, const float* __restrict__ Whh0,
               const float* __restrict__ bih0, const float* __restrict__ bhh0,
               const float* __restrict__ Wih1, const float* __restrict__ Whh1,
               const float* __restrict__ bih1, const float* __restrict__ bhh1,
               const float* __restrict__ fcw_g, const float* __restrict__ fcb_g,
               float* __restrict__ out)
{
    extern __shared__ float sm[];
    float* wt1 = sm + OFF_WT1;
    float* wt0 = sm + OFF_WT0;
    float* wx0 = sm + OFF_WX0;
    float* bs0 = sm + OFF_B0;
    float* bs1 = sm + OFF_B1;
    ull*   hsb = reinterpret_cast<ull*>(sm + OFF_HS);   // 4 x 1600 ull
    float* fcs = sm + OFF_FC;
    ull* h0b[2] = { hsb,          hsb + 1600 };
    ull* h1b[2] = { hsb + 3200,   hsb + 4800 };

    const int tid = threadIdx.x;
    const int b0  = blockIdx.x * NB;

    // ---------------- staging (prescaled, transposed, padded) ----------------
    for (int idx = tid; idx < 100*GC; idx += NTH) {
        int k = idx >> 8, col = idx & 255;
        int u = col >> 2, g = col & 3;
        float s = (g == 2) ? SCALE_T : SCALE_S;
        float v = 0.f;
        if (u < 50) {
            int row = g*50 + u;
            v = (k < 50) ? Wih1[row*50 + k] : Whh1[row*50 + (k - 50)];
        }
        wt1[idx] = v * s;
    }
    for (int idx = tid; idx < 50*GC; idx += NTH) {
        int k = idx >> 8, col = idx & 255;
        int u = col >> 2, g = col & 3;
        float s = (g == 2) ? SCALE_T : SCALE_S;
        wt0[idx] = (u < 50) ? Whh0[(g*50 + u)*50 + k] * s : 0.f;
    }
    if (tid < GC) {
        int u = tid >> 2, g = tid & 3;
        float s = (g == 2) ? SCALE_T : SCALE_S;
        int row = g*50 + u;
        wx0[tid] = (u < 50) ? Wih0[row] * s : 0.f;
        bs0[tid] = (u < 50) ? (bih0[row] + bhh0[row]) * s : 0.f;
        bs1[tid] = (u < 50) ? (bih1[row] + bhh1[row]) * s : 0.f;
    }
    if (tid < 50) fcs[tid] = fcw_g[tid];
    for (int idx = tid; idx < 4*1600; idx += NTH) hsb[idx] = 0ull;
    __syncthreads();

    // ---------------- per-thread geometry ----------------
    const int g  = tid & 7;              // row-group: rows 4g..4g+3
    const int c  = tid >> 3;             // col-chunk 0..31 (8 cols = 2 units)
    const int co = 8 * c;
    const int u0 = 2 * c;                // first unit (>=50 -> padding, act store guarded)

    const float* wt1c = wt1 + co;
    const float* wt0c = wt0 + co;
    const float* wx0c = wx0 + co;
    const float* b0c  = bs0 + co;
    const float* b1c  = bs1 + co;
    const float* xrow = x + (size_t)(b0 + 4*g) * T_LEN;   // row 4g; +r*T_LEN

    float c0s[8], c1s[8];                // c-state [unit J][row r]
    #pragma unroll
    for (int j = 0; j < 8; ++j) { c0s[j] = 0.f; c1s[j] = 0.f; }

    float xv[4], xn[4];

    // ---------------- prologue: h0(0) from x(0) + bias -> buf 0 ----------------
    {
        ull acc[16];
        initb16(acc, b0c);
        ull xs[4];
        #pragma unroll
        for (int r = 0; r < 4; ++r) { float p = xrow[r*T_LEN]; xs[r] = pack2(p, p); }
        mvk(acc, xs, wx0c);
        act_u<0>(acc, c0s, h0b[0], u0, g);
        act_u<1>(acc, c0s, h0b[0], u0, g);
        #pragma unroll
        for (int r = 0; r < 4; ++r) xv[r] = xrow[r*T_LEN + 1];
    }
    __syncthreads();

    // ---------------- main loop: ONE barrier per timestep ----------------
    // body(t): read h0(t), h1(t-1) from buf rd; single 50-k loop builds
    //   acc1 = L1 gates(t)  [h0·Wih1 + h1·Whh1]
    //   acc0 = L0 gates(t+1)[x(t+1)·Wih0 + h0·Whh0]
    // acts at end write h1(t), h0(t+1) into buf wr. BAR.
    for (int t = 0; t < T_LEN; ++t) {
        const int rd = t & 1, wr = (t + 1) & 1;
        const ull* h0rd = h0b[rd];
        const ull* h1rd = h1b[rd];

        ull acc0[16], acc1[16];
        initb16(acc1, b1c);
        initb16(acc0, b0c);
        {
            ull xs[4];
            #pragma unroll
            for (int r = 0; r < 4; ++r) xs[r] = pack2(xv[r], xv[r]);
            mvk(acc0, xs, wx0c);                          // x(t+1) rank-1
        }
        int tn = (t + 2 < T_LEN) ? t + 2 : T_LEN - 1;
        #pragma unroll
        for (int r = 0; r < 4; ++r) xn[r] = xrow[r*T_LEN + tn];   // prefetch x(t+2)

        #pragma unroll 2
        for (int k = 0; k < 50; ++k) {
            ull hh0[4], hh1[4];
            hload4(h0rd, k*32 + g*4, hh0);                // LDS.128 x2
            hload4(h1rd, k*32 + g*4, hh1);                // LDS.128 x2
            mvk(acc1, hh0, wt1c + k*GC);                  // L1: + h0·Wih1
            mvk(acc0, hh0, wt0c + k*GC);                  // L0(t+1): + h0·Whh0
            mvk(acc1, hh1, wt1c + (50 + k)*GC);           // L1: + h1·Whh1
        }

        act_u<0>(acc1, c1s, h1b[wr], u0, g);              // h1(t)
        act_u<1>(acc1, c1s, h1b[wr], u0, g);
        act_u<0>(acc0, c0s, h0b[wr], u0, g);              // h0(t+1)
        act_u<1>(acc0, c0s, h0b[wr], u0, g);

        #pragma unroll
        for (int r = 0; r < 4; ++r) xv[r] = xn[r];

        __syncthreads();
    }

    // ---------------- epilogue: FC over h1(511) (in buf (512)&1 = 0) ----------------
    if (tid < NB) {
        float s = fcb_g[0];
        const float* h1f = reinterpret_cast<const float*>(h1b[0]);
        #pragma unroll
        for (int u = 0; u < 50; ++u)
            s += fcs[u] * h1f[(u*32 + tid) * 2];   // low float of (h,h) pair
        out[b0 + tid] = s;
    }
}

extern "C" void kernel_launch(void* const* d_in, const int* in_sizes, int n_in,
                              void* d_out, int out_size)
{
    const float* x    = (const float*)d_in[0];
    const float* Wih0 = (const float*)d_in[1];
    const float* Whh0 = (const float*)d_in[2];
    const float* bih0 = (const float*)d_in[3];
    const float* bhh0 = (const float*)d_in[4];
    const float* Wih1 = (const float*)d_in[5];
    const float* Whh1 = (const float*)d_in[6];
    const float* bih1 = (const float*)d_in[7];
    const float* bhh1 = (const float*)d_in[8];
    const float* fcw  = (const float*)d_in[9];
    const float* fcb  = (const float*)d_in[10];
    float* out = (float*)d_out;

    const int B = in_sizes[0] / T_LEN;            // 4096
    const int grid = B / NB;                      // 128 CTAs
    const size_t smem = SMEMF * sizeof(float);    // 208128 B

    cudaFuncSetAttribute(lstm_v7_kernel,
                         cudaFuncAttributeMaxDynamicSharedMemorySize, (int)smem);

    lstm_v7_kernel<<<grid, NTH, smem>>>(
        x, Wih0, Whh0, bih0, bhh0, Wih1, Whh1, bih1, bhh1, fcw, fcb, out);
}